// round 15
// baseline (speedup 1.0000x reference)
#include <cuda_runtime.h>
#include <cuda_bf16.h>
#include <cstdint>

#define S_LEN 2048
#define HID   1024
#define NHEAD 16
#define HDIM  64
#define BATCH 2
#define MROWS (BATCH * S_LEN)   // 4096
#define K2    (2 * HID)         // 2048 (hi|lo split layout)

// ---------------------------------------------------------------------------
// Scratch (__device__ globals; no allocation allowed)
// ---------------------------------------------------------------------------
__device__ __nv_bfloat16 g_A[(size_t)MROWS * K2];          // [4096, 2048] = [hi|lo]
__device__ __nv_bfloat16 g_Bqkv[(size_t)(3 * HID) * K2];   // [3072, 2048] = [hi|lo]
__device__ __nv_bfloat16 g_Bout[(size_t)HID * K2];         // [1024, 2048]
// Pre-split attention operands: [B*NH, S, 128] rows = hi(64) | lo(64) bf16
__device__ __nv_bfloat16 g_Qsp[(size_t)BATCH * NHEAD * S_LEN * 128];
__device__ __nv_bfloat16 g_Ksp[(size_t)BATCH * NHEAD * S_LEN * 128];
__device__ __nv_bfloat16 g_Vsp[(size_t)BATCH * NHEAD * S_LEN * 128];

// ---------------------------------------------------------------------------
// Helpers
// ---------------------------------------------------------------------------
__device__ __forceinline__ uint32_t smem_u32(const void* p) {
    uint32_t a;
    asm("{ .reg .u64 t; cvta.to.shared.u64 t, %1; cvt.u32.u64 %0, t; }" : "=r"(a) : "l"(p));
    return a;
}
__device__ __forceinline__ void cpasync16(uint32_t s, const void* g) {
    asm volatile("cp.async.cg.shared.global [%0], [%1], 16;" :: "r"(s), "l"(g));
}
__device__ __forceinline__ void ldm_x4(uint32_t* r, uint32_t addr) {
    asm volatile("ldmatrix.sync.aligned.m8n8.x4.shared.b16 {%0,%1,%2,%3}, [%4];"
        : "=r"(r[0]), "=r"(r[1]), "=r"(r[2]), "=r"(r[3]) : "r"(addr));
}
__device__ __forceinline__ void ldm_x4_t(uint32_t* r, uint32_t addr) {
    asm volatile("ldmatrix.sync.aligned.m8n8.x4.trans.shared.b16 {%0,%1,%2,%3}, [%4];"
        : "=r"(r[0]), "=r"(r[1]), "=r"(r[2]), "=r"(r[3]) : "r"(addr));
}
__device__ __forceinline__ void mma16816(float* d, const uint32_t* a, uint32_t b0, uint32_t b1) {
    asm volatile("mma.sync.aligned.m16n8k16.row.col.f32.bf16.bf16.f32 "
        "{%0,%1,%2,%3}, {%4,%5,%6,%7}, {%8,%9}, {%0,%1,%2,%3};"
        : "+f"(d[0]), "+f"(d[1]), "+f"(d[2]), "+f"(d[3])
        : "r"(a[0]), "r"(a[1]), "r"(a[2]), "r"(a[3]), "r"(b0), "r"(b1));
}
__device__ __forceinline__ float ex2(float x) {
    float y; asm("ex2.approx.ftz.f32 %0, %1;" : "=f"(y) : "f"(x)); return y;
}
__device__ __forceinline__ uint32_t packlh(float lo, float hi) {
    uint32_t d; asm("cvt.rn.bf16x2.f32 %0, %1, %2;" : "=r"(d) : "f"(hi), "f"(lo)); return d;
}

#define QSCALE (0.125f * 1.44269504f)

// ---------------------------------------------------------------------------
// Split conversions: fp32 -> [hi | lo] bf16 (K-doubled layout)
// ---------------------------------------------------------------------------
__global__ __launch_bounds__(256) void split_A(
    const float* __restrict__ X, __nv_bfloat16* __restrict__ A, int K, int M)
{
    int i = blockIdx.x * 256 + threadIdx.x;
    if (i >= M * (K / 4)) return;
    int row = i / (K / 4);
    int c = (i % (K / 4)) * 4;
    float4 x = ((const float4*)X)[i];
    float xs[4] = {x.x, x.y, x.z, x.w};
    __nv_bfloat16 h[4], l[4];
#pragma unroll
    for (int q = 0; q < 4; q++) {
        h[q] = __float2bfloat16_rn(xs[q]);
        l[q] = __float2bfloat16_rn(xs[q] - __bfloat162float(h[q]));
    }
    __nv_bfloat16* base = A + (size_t)row * 2 * K + c;
    *(uint2*)(base)     = *(uint2*)h;
    *(uint2*)(base + K) = *(uint2*)l;
}

__global__ __launch_bounds__(256) void split_W(
    const float* __restrict__ W, __nv_bfloat16* __restrict__ Bo, int N, int K)
{
    __shared__ float t[32][33];
    int tx = threadIdx.x, ty = threadIdx.y;
    int n0 = blockIdx.x * 32, k0 = blockIdx.y * 32;
#pragma unroll
    for (int j = 0; j < 4; j++)
        t[ty + 8 * j][tx] = W[(size_t)(k0 + ty + 8 * j) * N + n0 + tx];
    __syncthreads();
#pragma unroll
    for (int j = 0; j < 4; j++) {
        float x = t[tx][ty + 8 * j];
        __nv_bfloat16 h = __float2bfloat16_rn(x);
        __nv_bfloat16 l = __float2bfloat16_rn(x - __bfloat162float(h));
        size_t o = (size_t)(n0 + ty + 8 * j) * 2 * K + k0 + tx;
        Bo[o]     = h;
        Bo[o + K] = l;
    }
}

// ---------------------------------------------------------------------------
// HMMA GEMM, fused 3-pass split, fat tiles:
//   D = Ahi.Bhi^T + Alo.Bhi^T + Ahi.Blo^T
// CTA tile 128x256, BK=32 real K, 3-stage cp.async ring, 8 warps (2M x 4N),
// warp tile 64x64, 1 CTA/SM.
//   QKV_EPI=0: C = fp32 (.. + bias)        (out projection -> d_out)
//   QKV_EPI=1: bf16 hi/lo pre-split head-major Qsp/Ksp/Vsp, Q scaled
// ---------------------------------------------------------------------------
#define BM 128
#define BN 256
#define BK 32
#define LDS 80
#define ATILE (BM * LDS)            // 10240
#define BTILE (BN * LDS)            // 20480
#define STG (2 * ATILE + 2 * BTILE) // 61440: Ahi|Alo|Bhi|Blo
#define NSTG 3
#define GEMM_SMEM (NSTG * STG)      // 184320

template <int QKV_EPI>
__global__ __launch_bounds__(256, 1) void hmma_gemm(
    const __nv_bfloat16* __restrict__ A, const __nv_bfloat16* __restrict__ B,
    const float* __restrict__ bias, float* __restrict__ C,
    __nv_bfloat16* __restrict__ Qsp, __nv_bfloat16* __restrict__ Ksp,
    __nv_bfloat16* __restrict__ Vsp, int N)
{
    extern __shared__ char sm[];
    uint32_t sb = smem_u32(sm);
    const int tid = threadIdx.x;
    const int lane = tid & 31;
    const int wid = tid >> 5;
    const int bm = blockIdx.y * BM;
    const int bn = blockIdx.x * BN;
    const int wm = (wid & 1) * 64;     // 2 warps in M
    const int wn = (wid >> 1) * 64;    // 4 warps in N

    float acc[4][8][4];                // [m16][n8][frag] = 128 regs
#pragma unroll
    for (int mt = 0; mt < 4; mt++)
#pragma unroll
        for (int nb = 0; nb < 8; nb++)
#pragma unroll
            for (int q = 0; q < 4; q++) acc[mt][nb][q] = 0.0f;

#define LOAD_STAGE(stg, k0) do {                                                \
    uint32_t so_ = sb + (stg) * STG;                                            \
    _Pragma("unroll")                                                           \
    for (int i_ = 0; i_ < 2; i_++) {                                            \
        int e_ = tid + i_ * 256;                                                \
        int r_ = e_ >> 2, c_ = e_ & 3;                                          \
        const __nv_bfloat16* ar_ = A + (size_t)(bm + r_) * K2 + (k0) + c_ * 8;  \
        cpasync16(so_ + r_ * LDS + c_ * 16, ar_);                               \
        cpasync16(so_ + ATILE + r_ * LDS + c_ * 16, ar_ + HID);                 \
    }                                                                           \
    _Pragma("unroll")                                                           \
    for (int i_ = 0; i_ < 4; i_++) {                                            \
        int e_ = tid + i_ * 256;                                                \
        int r_ = e_ >> 2, c_ = e_ & 3;                                          \
        const __nv_bfloat16* br_ = B + (size_t)(bn + r_) * K2 + (k0) + c_ * 8;  \
        cpasync16(so_ + 2 * ATILE + r_ * LDS + c_ * 16, br_);                   \
        cpasync16(so_ + 2 * ATILE + BTILE + r_ * LDS + c_ * 16, br_ + HID);     \
    }                                                                           \
} while (0)

    LOAD_STAGE(0, 0);
    asm volatile("cp.async.commit_group;" ::: "memory");
    LOAD_STAGE(1, BK);
    asm volatile("cp.async.commit_group;" ::: "memory");
    LOAD_STAGE(2, 2 * BK);
    asm volatile("cp.async.commit_group;" ::: "memory");

    const int NIT = HID / BK;          // 32
    int slot = 0;
    for (int it = 0; it < NIT; it++) {
        asm volatile("cp.async.wait_group 2;" ::: "memory");
        __syncthreads();

        uint32_t sA = sb + slot * STG;
        uint32_t sBh = sA + 2 * ATILE;
#pragma unroll
        for (int ks = 0; ks < 2; ks++) {
            // A fragments for 4 m16 chunks, hi+lo (loaded once per ks)
            uint32_t ah[4][4], al[4][4];
#pragma unroll
            for (int mt = 0; mt < 4; mt++) {
                uint32_t aaddr = sA + (wm + mt * 16 + (lane & 15)) * LDS
                               + ks * 32 + ((lane >> 4) << 4);
                ldm_x4(ah[mt], aaddr);
                ldm_x4(al[mt], aaddr + ATILE);
            }
            // Stream B n16 chunks; 3 passes from registers
#pragma unroll
            for (int nc = 0; nc < 4; nc++) {
                uint32_t bh[4], bl[4];
                uint32_t baddr = sBh + (wn + nc * 16 + (lane & 7) + ((lane >> 4) << 3)) * LDS
                               + ks * 32 + (((lane >> 3) & 1) << 4);
                ldm_x4(bh, baddr);
                ldm_x4(bl, baddr + BTILE);
#pragma unroll
                for (int mt = 0; mt < 4; mt++) {
                    mma16816(acc[mt][nc * 2 + 0], ah[mt], bh[0], bh[1]);
                    mma16816(acc[mt][nc * 2 + 1], ah[mt], bh[2], bh[3]);
                }
#pragma unroll
                for (int mt = 0; mt < 4; mt++) {
                    mma16816(acc[mt][nc * 2 + 0], al[mt], bh[0], bh[1]);
                    mma16816(acc[mt][nc * 2 + 1], al[mt], bh[2], bh[3]);
                }
#pragma unroll
                for (int mt = 0; mt < 4; mt++) {
                    mma16816(acc[mt][nc * 2 + 0], ah[mt], bl[0], bl[1]);
                    mma16816(acc[mt][nc * 2 + 1], ah[mt], bl[2], bl[3]);
                }
            }
        }

        __syncthreads();
        if (it + 3 < NIT) LOAD_STAGE(slot, (it + 3) * BK);
        asm volatile("cp.async.commit_group;" ::: "memory");
        slot = (slot == 2) ? 0 : slot + 1;
    }

    const int g = lane >> 2;
    const int tg = lane & 3;
#pragma unroll
    for (int mt = 0; mt < 4; mt++) {
        int row0 = bm + wm + mt * 16 + g;
#pragma unroll
        for (int nb = 0; nb < 8; nb++) {
            int col = bn + wn + nb * 8 + tg * 2;
            float bx = bias[col], by = bias[col + 1];
            float v00 = acc[mt][nb][0] + bx, v01 = acc[mt][nb][1] + by;
            float v10 = acc[mt][nb][2] + bx, v11 = acc[mt][nb][3] + by;
            if (QKV_EPI == 0) {
                float2 o0 = {v00, v01}, o1 = {v10, v11};
                *(float2*)(C + (size_t)row0 * N + col) = o0;
                *(float2*)(C + (size_t)(row0 + 8) * N + col) = o1;
            } else {
                int third = col >> 10;
                int head = (col >> 6) & 15;
                int dim = col & 63;
                __nv_bfloat16* base = (third == 0) ? Qsp : (third == 1) ? Ksp : Vsp;
                if (third == 0) { v00 *= QSCALE; v01 *= QSCALE; v10 *= QSCALE; v11 *= QSCALE; }
#pragma unroll
                for (int rr = 0; rr < 2; rr++) {
                    int m = row0 + rr * 8;
                    float va = rr ? v10 : v00, vb = rr ? v11 : v01;
                    int b_ = m >> 11, s_ = m & 2047;
                    size_t off = ((size_t)((b_ * NHEAD + head) * S_LEN + s_) << 7) + dim;
                    __nv_bfloat162 h2 = __floats2bfloat162_rn(va, vb);
                    uint32_t lo2 = packlh(va - __low2float(h2), vb - __high2float(h2));
                    *(uint32_t*)(base + off) = *(uint32_t*)&h2;
                    *(uint32_t*)(base + off + 64) = lo2;
                }
            }
        }
    }
#undef LOAD_STAGE
}

// ---------------------------------------------------------------------------
// HMMA flash attention (causal): cp.async 3-stage pipeline on pre-split bf16.
// CTA = 128 q rows x (b,h); 8 warps x 16 rows; 64-key tiles. (unchanged)
// ---------------------------------------------------------------------------
#define FROW 272
#define QBYTES   (128 * FROW)
#define KVSTAGE  (128 * FROW)
#define VOFF     (64 * FROW)
#define FA_SMEM  (QBYTES + 3 * KVSTAGE)

__global__ __launch_bounds__(256) void flash_attn_mma(
    const __nv_bfloat16* __restrict__ Qsp, const __nv_bfloat16* __restrict__ Ksp,
    const __nv_bfloat16* __restrict__ Vsp, __nv_bfloat16* __restrict__ Actx)
{
    extern __shared__ char smem[];
    uint32_t sb = smem_u32(smem);
    const int Tq = (S_LEN / 128 - 1) - blockIdx.x;   // heavy tiles first
    const int h = blockIdx.y, b = blockIdx.z;
    const int tid = threadIdx.x, lane = tid & 31, w = tid >> 5;
    const int g = lane >> 2, tg = lane & 3;
    const size_t bh = (size_t)(b * NHEAD + h) * S_LEN;
    const int KT = 2 * Tq + 2;

#pragma unroll
    for (int i = 0; i < 8; i++) {
        int e = tid + i * 256, r = e >> 4, c = e & 15;
        cpasync16(sb + r * FROW + c * 16,
                  Qsp + ((bh + Tq * 128 + r) << 7) + c * 8);
    }
#define LOAD_KV(slot, t) do {                                                  \
    uint32_t st_ = sb + QBYTES + (slot) * KVSTAGE;                             \
    _Pragma("unroll")                                                          \
    for (int i_ = 0; i_ < 4; i_++) {                                           \
        int e_ = tid + i_ * 256;                                               \
        int r_ = e_ >> 4, c_ = e_ & 15;                                        \
        size_t src_ = ((bh + (t) * 64 + r_) << 7) + c_ * 8;                    \
        cpasync16(st_ + r_ * FROW + c_ * 16, Ksp + src_);                      \
        cpasync16(st_ + VOFF + r_ * FROW + c_ * 16, Vsp + src_);               \
    }                                                                          \
} while (0)
    LOAD_KV(0, 0);
    asm volatile("cp.async.commit_group;" ::: "memory");
    if (1 < KT) LOAD_KV(1, 1);
    asm volatile("cp.async.commit_group;" ::: "memory");
    if (2 < KT) LOAD_KV(2, 2);
    asm volatile("cp.async.commit_group;" ::: "memory");

    float m0 = -1e30f, m1 = -1e30f, l0 = 0.0f, l1 = 0.0f;
    float acc[8][4];
#pragma unroll
    for (int nb = 0; nb < 8; nb++)
#pragma unroll
        for (int q = 0; q < 4; q++) acc[nb][q] = 0.0f;

    int slot = 0;
    for (int kt = 0; kt < KT; kt++) {
        asm volatile("cp.async.wait_group 2;" ::: "memory");
        __syncthreads();

        const uint32_t stK = sb + QBYTES + slot * KVSTAGE;
        const uint32_t stV = stK + VOFF;
        const int wrow = Tq * 128 + w * 16;
        const bool skip = (kt * 64 > wrow + 15);

        if (!skip) {
            float s[8][4];
#pragma unroll
            for (int nb = 0; nb < 8; nb++)
#pragma unroll
                for (int q = 0; q < 4; q++) s[nb][q] = 0.0f;

#pragma unroll
            for (int ks = 0; ks < 4; ks++) {
                uint32_t ah[4], al[4];
                uint32_t qaddr = sb + (w * 16 + (lane & 15)) * FROW
                               + ks * 32 + ((lane >> 4) << 4);
                ldm_x4(ah, qaddr);
                ldm_x4(al, qaddr + 128);
#pragma unroll
                for (int nb2 = 0; nb2 < 4; nb2++) {
                    uint32_t bk[4];
                    uint32_t kaddr = stK
                                   + (nb2 * 16 + (lane & 7) + ((lane >> 4) << 3)) * FROW
                                   + ks * 32 + (((lane >> 3) & 1) << 4);
                    ldm_x4(bk, kaddr);
                    mma16816(s[nb2 * 2],     ah, bk[0], bk[1]);
                    mma16816(s[nb2 * 2 + 1], ah, bk[2], bk[3]);
                    mma16816(s[nb2 * 2],     al, bk[0], bk[1]);
                    mma16816(s[nb2 * 2 + 1], al, bk[2], bk[3]);
                    ldm_x4(bk, kaddr + 128);
                    mma16816(s[nb2 * 2],     ah, bk[0], bk[1]);
                    mma16816(s[nb2 * 2 + 1], ah, bk[2], bk[3]);
                }
            }

            if (kt * 64 + 63 > wrow) {
                int r0g = wrow + g, r1g = r0g + 8;
#pragma unroll
                for (int nb = 0; nb < 8; nb++) {
                    int kc = kt * 64 + nb * 8 + tg * 2;
                    if (kc     > r0g) s[nb][0] = -1e30f;
                    if (kc + 1 > r0g) s[nb][1] = -1e30f;
                    if (kc     > r1g) s[nb][2] = -1e30f;
                    if (kc + 1 > r1g) s[nb][3] = -1e30f;
                }
            }

            float mx0 = -1e30f, mx1 = -1e30f;
#pragma unroll
            for (int nb = 0; nb < 8; nb++) {
                mx0 = fmaxf(mx0, fmaxf(s[nb][0], s[nb][1]));
                mx1 = fmaxf(mx1, fmaxf(s[nb][2], s[nb][3]));
            }
            mx0 = fmaxf(mx0, __shfl_xor_sync(0xffffffffu, mx0, 1));
            mx0 = fmaxf(mx0, __shfl_xor_sync(0xffffffffu, mx0, 2));
            mx1 = fmaxf(mx1, __shfl_xor_sync(0xffffffffu, mx1, 1));
            mx1 = fmaxf(mx1, __shfl_xor_sync(0xffffffffu, mx1, 2));
            float mn0 = fmaxf(m0, mx0), mn1 = fmaxf(m1, mx1);
            float sc0 = ex2(m0 - mn0), sc1 = ex2(m1 - mn1);
            float sum0 = 0.0f, sum1 = 0.0f;
            uint32_t aphi[4][4], aplo[4][4];
#pragma unroll
            for (int ks = 0; ks < 4; ks++)
#pragma unroll
                for (int hf = 0; hf < 2; hf++) {
                    int nb = ks * 2 + hf;
                    float p0 = ex2(s[nb][0] - mn0);
                    float p1 = ex2(s[nb][1] - mn0);
                    float p2 = ex2(s[nb][2] - mn1);
                    float p3 = ex2(s[nb][3] - mn1);
                    sum0 += p0 + p1; sum1 += p2 + p3;
                    __nv_bfloat162 t01 = __floats2bfloat162_rn(p0, p1);
                    __nv_bfloat162 t23 = __floats2bfloat162_rn(p2, p3);
                    aphi[ks][hf * 2]     = *(uint32_t*)&t01;
                    aphi[ks][hf * 2 + 1] = *(uint32_t*)&t23;
                    aplo[ks][hf * 2]     = packlh(p0 - __low2float(t01), p1 - __high2float(t01));
                    aplo[ks][hf * 2 + 1] = packlh(p2 - __low2float(t23), p3 - __high2float(t23));
                }
            sum0 += __shfl_xor_sync(0xffffffffu, sum0, 1);
            sum0 += __shfl_xor_sync(0xffffffffu, sum0, 2);
            sum1 += __shfl_xor_sync(0xffffffffu, sum1, 1);
            sum1 += __shfl_xor_sync(0xffffffffu, sum1, 2);
            l0 = l0 * sc0 + sum0; l1 = l1 * sc1 + sum1;
            m0 = mn0; m1 = mn1;
#pragma unroll
            for (int nb = 0; nb < 8; nb++) {
                acc[nb][0] *= sc0; acc[nb][1] *= sc0;
                acc[nb][2] *= sc1; acc[nb][3] *= sc1;
            }

#pragma unroll
            for (int ks = 0; ks < 4; ks++) {
#pragma unroll
                for (int nb2 = 0; nb2 < 4; nb2++) {
                    uint32_t bv[4];
                    uint32_t vaddr = stV
                                   + (ks * 16 + ((lane >> 3) & 1) * 8 + (lane & 7)) * FROW
                                   + nb2 * 32 + ((lane >> 4) << 4);
                    ldm_x4_t(bv, vaddr);
                    mma16816(acc[nb2 * 2],     aphi[ks], bv[0], bv[1]);
                    mma16816(acc[nb2 * 2 + 1], aphi[ks], bv[2], bv[3]);
                    mma16816(acc[nb2 * 2],     aplo[ks], bv[0], bv[1]);
                    mma16816(acc[nb2 * 2 + 1], aplo[ks], bv[2], bv[3]);
                    ldm_x4_t(bv, vaddr + 128);
                    mma16816(acc[nb2 * 2],     aphi[ks], bv[0], bv[1]);
                    mma16816(acc[nb2 * 2 + 1], aphi[ks], bv[2], bv[3]);
                }
            }
        }

        __syncthreads();
        if (kt + 3 < KT) LOAD_KV(slot, kt + 3);
        asm volatile("cp.async.commit_group;" ::: "memory");
        slot = (slot == 2) ? 0 : slot + 1;
    }

    // ---- write ctx directly in g_A split layout [row, hi|lo] ----
    float inv0 = 1.0f / l0, inv1 = 1.0f / l1;
    int row0 = b * S_LEN + Tq * 128 + w * 16 + g;
#pragma unroll
    for (int nb = 0; nb < 8; nb++) {
        int col = h * 64 + nb * 8 + tg * 2;
#pragma unroll
        for (int rr = 0; rr < 2; rr++) {
            float va = (rr ? acc[nb][2] * inv1 : acc[nb][0] * inv0);
            float vb = (rr ? acc[nb][3] * inv1 : acc[nb][1] * inv0);
            __nv_bfloat16* base = Actx + (size_t)(row0 + rr * 8) * K2 + col;
            __nv_bfloat162 h2 = __floats2bfloat162_rn(va, vb);
            uint32_t lo2 = packlh(va - __low2float(h2), vb - __high2float(h2));
            *(uint32_t*)(base)       = *(uint32_t*)&h2;
            *(uint32_t*)(base + HID) = lo2;
        }
    }
}

// ---------------------------------------------------------------------------
// Launch
// ---------------------------------------------------------------------------
extern "C" void kernel_launch(void* const* d_in, const int* in_sizes, int n_in,
                              void* d_out, int out_size)
{
    const float* hidden = (const float*)d_in[0];
    const float* W_qkv = (const float*)d_in[2];
    const float* b_qkv = (const float*)d_in[3];
    const float* W_out = (const float*)d_in[4];
    const float* b_out = (const float*)d_in[5];
    float* out = (float*)d_out;

    __nv_bfloat16 *A_d, *Bq_d, *Bo_d, *Qsp, *Ksp, *Vsp;
    cudaGetSymbolAddress((void**)&A_d, g_A);
    cudaGetSymbolAddress((void**)&Bq_d, g_Bqkv);
    cudaGetSymbolAddress((void**)&Bo_d, g_Bout);
    cudaGetSymbolAddress((void**)&Qsp, g_Qsp);
    cudaGetSymbolAddress((void**)&Ksp, g_Ksp);
    cudaGetSymbolAddress((void**)&Vsp, g_Vsp);

    cudaFuncSetAttribute(hmma_gemm<0>, cudaFuncAttributeMaxDynamicSharedMemorySize, GEMM_SMEM);
    cudaFuncSetAttribute(hmma_gemm<1>, cudaFuncAttributeMaxDynamicSharedMemorySize, GEMM_SMEM);
    cudaFuncSetAttribute(flash_attn_mma, cudaFuncAttributeMaxDynamicSharedMemorySize, FA_SMEM);

    // 1) Split inputs (hi|lo layouts)
    int n4 = MROWS * (HID / 4);
    split_A<<<(n4 + 255) / 256, 256>>>(hidden, A_d, HID, MROWS);
    split_W<<<dim3(3 * HID / 32, HID / 32), dim3(32, 8)>>>(W_qkv, Bq_d, 3 * HID, HID);
    split_W<<<dim3(HID / 32, HID / 32), dim3(32, 8)>>>(W_out, Bo_d, HID, HID);

    // 2) QKV projection -> pre-split head-major Qsp/Ksp/Vsp (Q scaled)
    hmma_gemm<1><<<dim3(3 * HID / BN, MROWS / BM), 256, GEMM_SMEM>>>(
        A_d, Bq_d, b_qkv, nullptr, Qsp, Ksp, Vsp, 3 * HID);

    // 3) Flash attention -> ctx directly in g_A split layout
    flash_attn_mma<<<dim3(S_LEN / 128, NHEAD, BATCH), 256, FA_SMEM>>>(
        Qsp, Ksp, Vsp, A_d);

    // 4) Output projection -> d_out
    hmma_gemm<0><<<dim3(HID / BN, MROWS / BM), 256, GEMM_SMEM>>>(
        A_d, Bo_d, b_out, out, nullptr, nullptr, nullptr, HID);
}

// round 17
// speedup vs baseline: 1.3993x; 1.3993x over previous
#include <cuda_runtime.h>
#include <cuda_fp16.h>
#include <cstdint>

#define S_LEN 2048
#define HID   1024
#define NHEAD 16
#define HDIM  64
#define BATCH 2
#define MROWS (BATCH * S_LEN)   // 4096
#define K2    (2 * HID)         // 2048 (hi|lo split layout for activations)

// ---------------------------------------------------------------------------
// Scratch (__device__ globals; no allocation allowed)
// ---------------------------------------------------------------------------
__device__ __half g_A[(size_t)MROWS * K2];          // [4096, 2048] = [hi|lo]
__device__ __half g_Bqkv[(size_t)(3 * HID) * HID];  // [3072, 1024] single fp16
__device__ __half g_Bout[(size_t)HID * HID];        // [1024, 1024] single fp16
// Attention operands: Q split [.,S,128]=hi|lo; K,V single [.,S,64]
__device__ __half g_Qsp[(size_t)BATCH * NHEAD * S_LEN * 128];
__device__ __half g_Ksp[(size_t)BATCH * NHEAD * S_LEN * 64];
__device__ __half g_Vsp[(size_t)BATCH * NHEAD * S_LEN * 64];

// ---------------------------------------------------------------------------
// Helpers
// ---------------------------------------------------------------------------
__device__ __forceinline__ uint32_t smem_u32(const void* p) {
    uint32_t a;
    asm("{ .reg .u64 t; cvta.to.shared.u64 t, %1; cvt.u32.u64 %0, t; }" : "=r"(a) : "l"(p));
    return a;
}
__device__ __forceinline__ void cpasync16(uint32_t s, const void* g) {
    asm volatile("cp.async.cg.shared.global [%0], [%1], 16;" :: "r"(s), "l"(g));
}
__device__ __forceinline__ void ldm_x4(uint32_t* r, uint32_t addr) {
    asm volatile("ldmatrix.sync.aligned.m8n8.x4.shared.b16 {%0,%1,%2,%3}, [%4];"
        : "=r"(r[0]), "=r"(r[1]), "=r"(r[2]), "=r"(r[3]) : "r"(addr));
}
__device__ __forceinline__ void ldm_x4_t(uint32_t* r, uint32_t addr) {
    asm volatile("ldmatrix.sync.aligned.m8n8.x4.trans.shared.b16 {%0,%1,%2,%3}, [%4];"
        : "=r"(r[0]), "=r"(r[1]), "=r"(r[2]), "=r"(r[3]) : "r"(addr));
}
// fp16 MMA, fp32 accum
__device__ __forceinline__ void mma16816(float* d, const uint32_t* a, uint32_t b0, uint32_t b1) {
    asm volatile("mma.sync.aligned.m16n8k16.row.col.f32.f16.f16.f32 "
        "{%0,%1,%2,%3}, {%4,%5,%6,%7}, {%8,%9}, {%0,%1,%2,%3};"
        : "+f"(d[0]), "+f"(d[1]), "+f"(d[2]), "+f"(d[3])
        : "r"(a[0]), "r"(a[1]), "r"(a[2]), "r"(a[3]), "r"(b0), "r"(b1));
}
__device__ __forceinline__ float ex2(float x) {
    float y; asm("ex2.approx.ftz.f32 %0, %1;" : "=f"(y) : "f"(x)); return y;
}
// pack two floats into f16x2 (lo arg -> low half, hi arg -> high half)
__device__ __forceinline__ uint32_t packlh(float lo, float hi) {
    uint32_t d; asm("cvt.rn.f16x2.f32 %0, %1, %2;" : "=r"(d) : "f"(hi), "f"(lo)); return d;
}
__device__ __forceinline__ uint32_t pack2h(float a, float b) {  // a->low, b->high
    uint32_t d; asm("cvt.rn.f16x2.f32 %0, %1, %2;" : "=r"(d) : "f"(b), "f"(a)); return d;
}
__device__ __forceinline__ float low_h(uint32_t v)  { __half h = __ushort_as_half((unsigned short)(v & 0xFFFF)); return __half2float(h); }
__device__ __forceinline__ float high_h(uint32_t v) { __half h = __ushort_as_half((unsigned short)(v >> 16));   return __half2float(h); }

#define QSCALE (0.125f * 1.44269504f)

// ---------------------------------------------------------------------------
// Split conversions
// ---------------------------------------------------------------------------
// X [M,K] fp32 -> A [M,2K] fp16 = [hi | lo]
__global__ __launch_bounds__(256) void split_A(
    const float* __restrict__ X, __half* __restrict__ A, int K, int M)
{
    int i = blockIdx.x * 256 + threadIdx.x;
    if (i >= M * (K / 4)) return;
    int row = i / (K / 4);
    int c = (i % (K / 4)) * 4;
    float4 x = ((const float4*)X)[i];
    float xs[4] = {x.x, x.y, x.z, x.w};
    __half h[4], l[4];
#pragma unroll
    for (int q = 0; q < 4; q++) {
        h[q] = __float2half_rn(xs[q]);
        l[q] = __float2half_rn(xs[q] - __half2float(h[q]));
    }
    __half* base = A + (size_t)row * 2 * K + c;
    *(uint2*)(base)     = *(uint2*)h;
    *(uint2*)(base + K) = *(uint2*)l;
}

// W [K,N] fp32 -> B [N,K] fp16 single (transposed to K-major)
__global__ __launch_bounds__(256) void split_W(
    const float* __restrict__ W, __half* __restrict__ Bo, int N, int K)
{
    __shared__ float t[32][33];
    int tx = threadIdx.x, ty = threadIdx.y;
    int n0 = blockIdx.x * 32, k0 = blockIdx.y * 32;
#pragma unroll
    for (int j = 0; j < 4; j++)
        t[ty + 8 * j][tx] = W[(size_t)(k0 + ty + 8 * j) * N + n0 + tx];
    __syncthreads();
#pragma unroll
    for (int j = 0; j < 4; j++) {
        float x = t[tx][ty + 8 * j];
        Bo[(size_t)(n0 + ty + 8 * j) * K + k0 + tx] = __float2half_rn(x);
    }
}

// ---------------------------------------------------------------------------
// HMMA GEMM, fused 2-pass fp16 split:
//   D = Ahi.B^T + Alo.B^T    (B single fp16)
// CTA tile 128x128, BK=32, 3-stage cp.async ring, 8 warps (2M x 4N),
// warp tile 64x32, 2 CTA/SM.
//   QKV_EPI=0: C = fp32 (.. + bias)        (out projection -> d_out)
//   QKV_EPI=1: Q hi/lo split + K,V single, head-major, Q scaled
// ---------------------------------------------------------------------------
#define BM 128
#define BN 128
#define BK 32
#define LDS 80
#define TILE (BM * LDS)            // 10240
#define STG (3 * TILE)             // Ahi|Alo|B = 30720
#define NSTG 3
#define GEMM_SMEM (NSTG * STG)     // 92160

template <int QKV_EPI>
__global__ __launch_bounds__(256, 2) void hmma_gemm(
    const __half* __restrict__ A, const __half* __restrict__ B,
    const float* __restrict__ bias, float* __restrict__ C,
    __half* __restrict__ Qsp, __half* __restrict__ Ksp,
    __half* __restrict__ Vsp, int N)
{
    extern __shared__ char sm[];
    uint32_t sb = smem_u32(sm);
    const int tid = threadIdx.x;
    const int lane = tid & 31;
    const int wid = tid >> 5;
    const int bm = blockIdx.y * BM;
    const int bn = blockIdx.x * BN;
    const int wm = (wid & 1) * 64;     // 2 warps in M
    const int wn = (wid >> 1) * 32;    // 4 warps in N

    float acc[4][4][4];                // [m16][n8][frag] = 64 regs
#pragma unroll
    for (int mt = 0; mt < 4; mt++)
#pragma unroll
        for (int nb = 0; nb < 4; nb++)
#pragma unroll
            for (int q = 0; q < 4; q++) acc[mt][nb][q] = 0.0f;

#define LOAD_STAGE(stg, k0) do {                                                \
    uint32_t so_ = sb + (stg) * STG;                                            \
    _Pragma("unroll")                                                           \
    for (int i_ = 0; i_ < 2; i_++) {                                            \
        int e_ = tid + i_ * 256;                                                \
        int r_ = e_ >> 2, c_ = e_ & 3;                                          \
        const __half* ar_ = A + (size_t)(bm + r_) * K2 + (k0) + c_ * 8;         \
        cpasync16(so_ + r_ * LDS + c_ * 16, ar_);                               \
        cpasync16(so_ + TILE + r_ * LDS + c_ * 16, ar_ + HID);                  \
        cpasync16(so_ + 2 * TILE + r_ * LDS + c_ * 16,                          \
                  B + (size_t)(bn + r_) * HID + (k0) + c_ * 8);                 \
    }                                                                           \
} while (0)

    LOAD_STAGE(0, 0);
    asm volatile("cp.async.commit_group;" ::: "memory");
    LOAD_STAGE(1, BK);
    asm volatile("cp.async.commit_group;" ::: "memory");
    LOAD_STAGE(2, 2 * BK);
    asm volatile("cp.async.commit_group;" ::: "memory");

    const int NIT = HID / BK;          // 32
    int slot = 0;
    for (int it = 0; it < NIT; it++) {
        asm volatile("cp.async.wait_group 2;" ::: "memory");
        __syncthreads();

        uint32_t sA = sb + slot * STG;
        uint32_t sB = sA + 2 * TILE;
#pragma unroll
        for (int ks = 0; ks < 2; ks++) {
            // B fragments: 2 n16 chunks (single fp16)
            uint32_t bh[2][4];
#pragma unroll
            for (int nc = 0; nc < 2; nc++) {
                uint32_t baddr = sB + (wn + nc * 16 + (lane & 7) + ((lane >> 4) << 3)) * LDS
                               + ks * 32 + (((lane >> 3) & 1) << 4);
                ldm_x4(bh[nc], baddr);
            }
            // pass 1: Ahi.B
#pragma unroll
            for (int mt = 0; mt < 4; mt++) {
                uint32_t ah[4];
                uint32_t aaddr = sA + (wm + mt * 16 + (lane & 15)) * LDS
                               + ks * 32 + ((lane >> 4) << 4);
                ldm_x4(ah, aaddr);
                mma16816(acc[mt][0], ah, bh[0][0], bh[0][1]);
                mma16816(acc[mt][1], ah, bh[0][2], bh[0][3]);
                mma16816(acc[mt][2], ah, bh[1][0], bh[1][1]);
                mma16816(acc[mt][3], ah, bh[1][2], bh[1][3]);
            }
            // pass 2: Alo.B
#pragma unroll
            for (int mt = 0; mt < 4; mt++) {
                uint32_t al[4];
                uint32_t aaddr = sA + TILE + (wm + mt * 16 + (lane & 15)) * LDS
                               + ks * 32 + ((lane >> 4) << 4);
                ldm_x4(al, aaddr);
                mma16816(acc[mt][0], al, bh[0][0], bh[0][1]);
                mma16816(acc[mt][1], al, bh[0][2], bh[0][3]);
                mma16816(acc[mt][2], al, bh[1][0], bh[1][1]);
                mma16816(acc[mt][3], al, bh[1][2], bh[1][3]);
            }
        }

        __syncthreads();
        if (it + 3 < NIT) LOAD_STAGE(slot, (it + 3) * BK);
        asm volatile("cp.async.commit_group;" ::: "memory");
        slot = (slot == 2) ? 0 : slot + 1;
    }

    const int g = lane >> 2;
    const int tg = lane & 3;
#pragma unroll
    for (int mt = 0; mt < 4; mt++) {
        int row0 = bm + wm + mt * 16 + g;
#pragma unroll
        for (int nb = 0; nb < 4; nb++) {
            int col = bn + wn + nb * 8 + tg * 2;
            float bx = bias[col], by = bias[col + 1];
            float v00 = acc[mt][nb][0] + bx, v01 = acc[mt][nb][1] + by;
            float v10 = acc[mt][nb][2] + bx, v11 = acc[mt][nb][3] + by;
            if (QKV_EPI == 0) {
                float2 o0 = {v00, v01}, o1 = {v10, v11};
                *(float2*)(C + (size_t)row0 * N + col) = o0;
                *(float2*)(C + (size_t)(row0 + 8) * N + col) = o1;
            } else {
                int third = col >> 10;
                int head = (col >> 6) & 15;
                int dim = col & 63;
                if (third == 0) { v00 *= QSCALE; v01 *= QSCALE; v10 *= QSCALE; v11 *= QSCALE; }
#pragma unroll
                for (int rr = 0; rr < 2; rr++) {
                    int m = row0 + rr * 8;
                    float va = rr ? v10 : v00, vb = rr ? v11 : v01;
                    int b_ = m >> 11, s_ = m & 2047;
                    size_t bhs = (size_t)(b_ * NHEAD + head) * S_LEN + s_;
                    if (third == 0) {
                        // Q: split hi/lo, 128-wide rows
                        size_t off = (bhs << 7) + dim;
                        uint32_t h2 = pack2h(va, vb);
                        uint32_t lo2 = packlh(va - low_h(h2), vb - high_h(h2));
                        *(uint32_t*)(Qsp + off) = h2;
                        *(uint32_t*)(Qsp + off + 64) = lo2;
                    } else {
                        // K/V: single fp16, 64-wide rows
                        size_t off = (bhs << 6) + dim;
                        __half* dst = (third == 1) ? Ksp : Vsp;
                        *(uint32_t*)(dst + off) = pack2h(va, vb);
                    }
                }
            }
        }
    }
#undef LOAD_STAGE
}

// ---------------------------------------------------------------------------
// HMMA flash attention (causal), 2-pass fp16:
//   S = Qhi.K^T + Qlo.K^T ;  ctx += Phi.V + Plo.V
// CTA = 128 q rows x (b,h); 8 warps x 16 rows; 64-key tiles, 3-stage cp.async.
// Q rows 272B stride (hi128|lo128); K,V rows 144B stride (128B data).
// ---------------------------------------------------------------------------
#define FROW 272
#define KROW 144
#define QBYTES   (128 * FROW)           // 34816
#define VOFF     (64 * KROW)            // 9216
#define KVSTAGE  (2 * 64 * KROW)        // 18432
#define FA_SMEM  (QBYTES + 3 * KVSTAGE) // 90112

__global__ __launch_bounds__(256) void flash_attn_mma(
    const __half* __restrict__ Qsp, const __half* __restrict__ Ksp,
    const __half* __restrict__ Vsp, __half* __restrict__ Actx)
{
    extern __shared__ char smem[];
    uint32_t sb = smem_u32(smem);
    const int Tq = (S_LEN / 128 - 1) - blockIdx.x;   // heavy tiles first
    const int h = blockIdx.y, b = blockIdx.z;
    const int tid = threadIdx.x, lane = tid & 31, w = tid >> 5;
    const int g = lane >> 2, tg = lane & 3;
    const size_t bh = (size_t)(b * NHEAD + h) * S_LEN;
    const int KT = 2 * Tq + 2;

    // Q tile: 128 rows x 256B (hi|lo)
#pragma unroll
    for (int i = 0; i < 8; i++) {
        int e = tid + i * 256, r = e >> 4, c = e & 15;
        cpasync16(sb + r * FROW + c * 16,
                  Qsp + ((bh + Tq * 128 + r) << 7) + c * 8);
    }
// K/V: 64 rows x 8 chunks of 16B each -> 512 elements per operand = 2 iters
#define LOAD_KV(slot, t) do {                                                  \
    uint32_t st_ = sb + QBYTES + (slot) * KVSTAGE;                             \
    _Pragma("unroll")                                                          \
    for (int i_ = 0; i_ < 2; i_++) {                                           \
        int e_ = tid + i_ * 256;                                               \
        int r_ = e_ >> 3, c_ = e_ & 7;                                         \
        size_t src_ = ((bh + (t) * 64 + r_) << 6) + c_ * 8;                    \
        cpasync16(st_ + r_ * KROW + c_ * 16, Ksp + src_);                      \
        cpasync16(st_ + VOFF + r_ * KROW + c_ * 16, Vsp + src_);               \
    }                                                                          \
} while (0)
    LOAD_KV(0, 0);
    asm volatile("cp.async.commit_group;" ::: "memory");
    if (1 < KT) LOAD_KV(1, 1);
    asm volatile("cp.async.commit_group;" ::: "memory");
    if (2 < KT) LOAD_KV(2, 2);
    asm volatile("cp.async.commit_group;" ::: "memory");

    float m0 = -1e30f, m1 = -1e30f, l0 = 0.0f, l1 = 0.0f;
    float acc[8][4];
#pragma unroll
    for (int nb = 0; nb < 8; nb++)
#pragma unroll
        for (int q = 0; q < 4; q++) acc[nb][q] = 0.0f;

    int slot = 0;
    for (int kt = 0; kt < KT; kt++) {
        asm volatile("cp.async.wait_group 2;" ::: "memory");
        __syncthreads();

        const uint32_t stK = sb + QBYTES + slot * KVSTAGE;
        const uint32_t stV = stK + VOFF;
        const int wrow = Tq * 128 + w * 16;
        const bool skip = (kt * 64 > wrow + 15);

        if (!skip) {
            // ---- S[16,64] = Qhi.K^T + Qlo.K^T ----
            float s[8][4];
#pragma unroll
            for (int nb = 0; nb < 8; nb++)
#pragma unroll
                for (int q = 0; q < 4; q++) s[nb][q] = 0.0f;

#pragma unroll
            for (int ks = 0; ks < 4; ks++) {
                uint32_t ah[4], al[4];
                uint32_t qaddr = sb + (w * 16 + (lane & 15)) * FROW
                               + ks * 32 + ((lane >> 4) << 4);
                ldm_x4(ah, qaddr);
                ldm_x4(al, qaddr + 128);
#pragma unroll
                for (int nb2 = 0; nb2 < 4; nb2++) {
                    uint32_t bk[4];
                    uint32_t kaddr = stK
                                   + (nb2 * 16 + (lane & 7) + ((lane >> 4) << 3)) * KROW
                                   + ks * 32 + (((lane >> 3) & 1) << 4);
                    ldm_x4(bk, kaddr);
                    mma16816(s[nb2 * 2],     ah, bk[0], bk[1]);
                    mma16816(s[nb2 * 2 + 1], ah, bk[2], bk[3]);
                    mma16816(s[nb2 * 2],     al, bk[0], bk[1]);
                    mma16816(s[nb2 * 2 + 1], al, bk[2], bk[3]);
                }
            }

            // ---- causal mask (diagonal tiles) ----
            if (kt * 64 + 63 > wrow) {
                int r0g = wrow + g, r1g = r0g + 8;
#pragma unroll
                for (int nb = 0; nb < 8; nb++) {
                    int kc = kt * 64 + nb * 8 + tg * 2;
                    if (kc     > r0g) s[nb][0] = -1e30f;
                    if (kc + 1 > r0g) s[nb][1] = -1e30f;
                    if (kc     > r1g) s[nb][2] = -1e30f;
                    if (kc + 1 > r1g) s[nb][3] = -1e30f;
                }
            }

            // ---- online softmax (base 2), P -> fp16 hi/lo A-fragments ----
            float mx0 = -1e30f, mx1 = -1e30f;
#pragma unroll
            for (int nb = 0; nb < 8; nb++) {
                mx0 = fmaxf(mx0, fmaxf(s[nb][0], s[nb][1]));
                mx1 = fmaxf(mx1, fmaxf(s[nb][2], s[nb][3]));
            }
            mx0 = fmaxf(mx0, __shfl_xor_sync(0xffffffffu, mx0, 1));
            mx0 = fmaxf(mx0, __shfl_xor_sync(0xffffffffu, mx0, 2));
            mx1 = fmaxf(mx1, __shfl_xor_sync(0xffffffffu, mx1, 1));
            mx1 = fmaxf(mx1, __shfl_xor_sync(0xffffffffu, mx1, 2));
            float mn0 = fmaxf(m0, mx0), mn1 = fmaxf(m1, mx1);
            float sc0 = ex2(m0 - mn0), sc1 = ex2(m1 - mn1);
            float sum0 = 0.0f, sum1 = 0.0f;
            uint32_t aphi[4][4], aplo[4][4];
#pragma unroll
            for (int ks = 0; ks < 4; ks++)
#pragma unroll
                for (int hf = 0; hf < 2; hf++) {
                    int nb = ks * 2 + hf;
                    float p0 = ex2(s[nb][0] - mn0);
                    float p1 = ex2(s[nb][1] - mn0);
                    float p2 = ex2(s[nb][2] - mn1);
                    float p3 = ex2(s[nb][3] - mn1);
                    sum0 += p0 + p1; sum1 += p2 + p3;
                    uint32_t t01 = pack2h(p0, p1);
                    uint32_t t23 = pack2h(p2, p3);
                    aphi[ks][hf * 2]     = t01;
                    aphi[ks][hf * 2 + 1] = t23;
                    aplo[ks][hf * 2]     = packlh(p0 - low_h(t01), p1 - high_h(t01));
                    aplo[ks][hf * 2 + 1] = packlh(p2 - low_h(t23), p3 - high_h(t23));
                }
            sum0 += __shfl_xor_sync(0xffffffffu, sum0, 1);
            sum0 += __shfl_xor_sync(0xffffffffu, sum0, 2);
            sum1 += __shfl_xor_sync(0xffffffffu, sum1, 1);
            sum1 += __shfl_xor_sync(0xffffffffu, sum1, 2);
            l0 = l0 * sc0 + sum0; l1 = l1 * sc1 + sum1;
            m0 = mn0; m1 = mn1;
#pragma unroll
            for (int nb = 0; nb < 8; nb++) {
                acc[nb][0] *= sc0; acc[nb][1] *= sc0;
                acc[nb][2] *= sc1; acc[nb][3] *= sc1;
            }

            // ---- ctx += Phi.V + Plo.V (V single, trans-ldmatrix) ----
#pragma unroll
            for (int ks = 0; ks < 4; ks++) {
#pragma unroll
                for (int nb2 = 0; nb2 < 4; nb2++) {
                    uint32_t bv[4];
                    uint32_t vaddr = stV
                                   + (ks * 16 + ((lane >> 3) & 1) * 8 + (lane & 7)) * KROW
                                   + nb2 * 32 + ((lane >> 4) << 4);
                    ldm_x4_t(bv, vaddr);
                    mma16816(acc[nb2 * 2],     aphi[ks], bv[0], bv[1]);
                    mma16816(acc[nb2 * 2 + 1], aphi[ks], bv[2], bv[3]);
                    mma16816(acc[nb2 * 2],     aplo[ks], bv[0], bv[1]);
                    mma16816(acc[nb2 * 2 + 1], aplo[ks], bv[2], bv[3]);
                }
            }
        }

        __syncthreads();
        if (kt + 3 < KT) LOAD_KV(slot, kt + 3);
        asm volatile("cp.async.commit_group;" ::: "memory");
        slot = (slot == 2) ? 0 : slot + 1;
    }

    // ---- write ctx directly in g_A split layout [row, hi|lo] ----
    float inv0 = 1.0f / l0, inv1 = 1.0f / l1;
    int row0 = b * S_LEN + Tq * 128 + w * 16 + g;
#pragma unroll
    for (int nb = 0; nb < 8; nb++) {
        int col = h * 64 + nb * 8 + tg * 2;
#pragma unroll
        for (int rr = 0; rr < 2; rr++) {
            float va = (rr ? acc[nb][2] * inv1 : acc[nb][0] * inv0);
            float vb = (rr ? acc[nb][3] * inv1 : acc[nb][1] * inv0);
            __half* base = Actx + (size_t)(row0 + rr * 8) * K2 + col;
            uint32_t h2 = pack2h(va, vb);
            uint32_t lo2 = packlh(va - low_h(h2), vb - high_h(h2));
            *(uint32_t*)(base)       = h2;
            *(uint32_t*)(base + HID) = lo2;
        }
    }
}

// ---------------------------------------------------------------------------
// Launch
// ---------------------------------------------------------------------------
extern "C" void kernel_launch(void* const* d_in, const int* in_sizes, int n_in,
                              void* d_out, int out_size)
{
    const float* hidden = (const float*)d_in[0];
    const float* W_qkv = (const float*)d_in[2];
    const float* b_qkv = (const float*)d_in[3];
    const float* W_out = (const float*)d_in[4];
    const float* b_out = (const float*)d_in[5];
    float* out = (float*)d_out;

    __half *A_d, *Bq_d, *Bo_d, *Qsp, *Ksp, *Vsp;
    cudaGetSymbolAddress((void**)&A_d, g_A);
    cudaGetSymbolAddress((void**)&Bq_d, g_Bqkv);
    cudaGetSymbolAddress((void**)&Bo_d, g_Bout);
    cudaGetSymbolAddress((void**)&Qsp, g_Qsp);
    cudaGetSymbolAddress((void**)&Ksp, g_Ksp);
    cudaGetSymbolAddress((void**)&Vsp, g_Vsp);

    cudaFuncSetAttribute(hmma_gemm<0>, cudaFuncAttributeMaxDynamicSharedMemorySize, GEMM_SMEM);
    cudaFuncSetAttribute(hmma_gemm<1>, cudaFuncAttributeMaxDynamicSharedMemorySize, GEMM_SMEM);
    cudaFuncSetAttribute(flash_attn_mma, cudaFuncAttributeMaxDynamicSharedMemorySize, FA_SMEM);

    // 1) Split inputs (A hi|lo; W single fp16, transposed)
    int n4 = MROWS * (HID / 4);
    split_A<<<(n4 + 255) / 256, 256>>>(hidden, A_d, HID, MROWS);
    split_W<<<dim3(3 * HID / 32, HID / 32), dim3(32, 8)>>>(W_qkv, Bq_d, 3 * HID, HID);
    split_W<<<dim3(HID / 32, HID / 32), dim3(32, 8)>>>(W_out, Bo_d, HID, HID);

    // 2) QKV projection -> Q split + K,V single, head-major (Q scaled)
    hmma_gemm<1><<<dim3(3 * HID / BN, MROWS / BM), 256, GEMM_SMEM>>>(
        A_d, Bq_d, b_qkv, nullptr, Qsp, Ksp, Vsp, 3 * HID);

    // 3) Flash attention -> ctx directly in g_A split layout
    flash_attn_mma<<<dim3(S_LEN / 128, NHEAD, BATCH), 256, FA_SMEM>>>(
        Qsp, Ksp, Vsp, A_d);

    // 4) Output projection -> d_out
    hmma_gemm<0><<<dim3(HID / BN, MROWS / BM), 256, GEMM_SMEM>>>(
        A_d, Bo_d, b_out, out, nullptr, nullptr, nullptr, HID);
}